// round 8
// baseline (speedup 1.0000x reference)
#include <cuda_runtime.h>
#include <cuda_bf16.h>
#include <cstdint>
#include <math.h>

#define SEQ  8192
#define DIM  1024
#define NOUT 4096

// ---------------- device scratch (no allocations allowed) ----------------
__device__ __nv_bfloat16 g_x_hi[SEQ * DIM];
__device__ __nv_bfloat16 g_x_lo[SEQ * DIM];
__device__ __nv_bfloat16 g_w_hi[NOUT * DIM];
__device__ __nv_bfloat16 g_w_lo[NOUT * DIM];

// ---------------- PTX helpers (base-target sm_80/sm_90 features only) ----------------
__device__ __forceinline__ uint32_t smem_u32(const void* p) {
    uint32_t a;
    asm("{ .reg .u64 t; cvta.to.shared.u64 t, %1; cvt.u32.u64 %0, t; }" : "=r"(a) : "l"(p));
    return a;
}
__device__ __forceinline__ void cp_async16(uint32_t smem, const void* gmem) {
    asm volatile("cp.async.cg.shared.global [%0], [%1], 16;" :: "r"(smem), "l"(gmem) : "memory");
}
__device__ __forceinline__ void cp_commit() {
    asm volatile("cp.async.commit_group;" ::: "memory");
}
template <int N>
__device__ __forceinline__ void cp_wait() {
    asm volatile("cp.async.wait_group %0;" :: "n"(N) : "memory");
}
__device__ __forceinline__ void ldsm_x4(uint32_t* r, uint32_t addr) {
    asm volatile("ldmatrix.sync.aligned.m8n8.x4.shared.b16 {%0,%1,%2,%3}, [%4];"
                 : "=r"(r[0]), "=r"(r[1]), "=r"(r[2]), "=r"(r[3]) : "r"(addr));
}
__device__ __forceinline__ void mma_bf16(float* c, const uint32_t* a, const uint32_t* b) {
    asm volatile(
        "mma.sync.aligned.m16n8k16.row.col.f32.bf16.bf16.f32 "
        "{%0,%1,%2,%3}, {%4,%5,%6,%7}, {%8,%9}, {%0,%1,%2,%3};"
        : "+f"(c[0]), "+f"(c[1]), "+f"(c[2]), "+f"(c[3])
        : "r"(a[0]), "r"(a[1]), "r"(a[2]), "r"(a[3]), "r"(b[0]), "r"(b[1]));
}

// ---------------- fp32 -> bf16 hi/lo split (x and W in ONE kernel) ----------------
static constexpr int XBLOCKS = (SEQ * DIM / 4) / 256;   // 8192
static constexpr int WBLOCKS = (NOUT * DIM / 4) / 256;  // 4096

__global__ void split_all_kernel(const float* __restrict__ x, const float* __restrict__ W) {
    const int bid = blockIdx.x;
    const float* src;
    __nv_bfloat16 *hi, *lo;
    int i;
    if (bid < XBLOCKS) {
        src = x; hi = g_x_hi; lo = g_x_lo;
        i = bid * 256 + threadIdx.x;
    } else {
        src = W; hi = g_w_hi; lo = g_w_lo;
        i = (bid - XBLOCKS) * 256 + threadIdx.x;
    }
    float4 v = reinterpret_cast<const float4*>(src)[i];
    float vv[4] = {v.x, v.y, v.z, v.w};
    unsigned short h[4], l[4];
#pragma unroll
    for (int j = 0; j < 4; j++) {
        __nv_bfloat16 hb = __float2bfloat16(vv[j]);
        __nv_bfloat16 lb = __float2bfloat16(vv[j] - __bfloat162float(hb));
        h[j] = __bfloat16_as_ushort(hb);
        l[j] = __bfloat16_as_ushort(lb);
    }
    reinterpret_cast<ushort4*>(hi)[i] = make_ushort4(h[0], h[1], h[2], h[3]);
    reinterpret_cast<ushort4*>(lo)[i] = make_ushort4(l[0], l[1], l[2], l[3]);
}

// ---------------- mma.sync GEMM + bias + tanh ----------------
// CTA tile 128x128, K-stage 64 bf16, 3 fused terms -> 48 stage-iterations.
// 8 warps in 2(M) x 4(N) grid; warp tile 64x32 via m16n8k16.
// PADDED-LINEAR smem layout (144B rows = 9 x 16B units): LDSM bank-conflict-free
// with NO xor swizzle -> every LDSM/STS address is base + compile-time constant.
static constexpr int NSTAGES  = 3;
static constexpr int ROW_B    = 144;                 // 128B data + 16B pad
static constexpr int A_BYTES  = 128 * ROW_B;         // 18432
static constexpr int STAGE_B  = 2 * A_BYTES;         // 36864
static constexpr int SMEM_GB  = NSTAGES * STAGE_B;   // 110592 (x2 CTA = 216KB/SM)
static constexpr int ITERS    = 3 * (DIM / 64);      // 48

__global__ __launch_bounds__(256, 2)
void gemm_kernel(const float* __restrict__ bias, float* __restrict__ out) {
    extern __shared__ char smem[];
    const uint32_t sb = smem_u32(smem);
    const int tid  = threadIdx.x;
    const int lane = tid & 31;
    const int wid  = tid >> 5;
    const int wm   = wid >> 2;       // 0..1 -> 64 rows
    const int wn   = wid & 3;        // 0..3 -> 32 cols
    const int m_base = blockIdx.y * 128;
    const int n_base = blockIdx.x * 128;

    // cp.async addressing: thread t -> row r = t>>1 (0..127), half h = t&1, 4x16B units
    const int r_ld = tid >> 1;
    const int h_ld = tid & 1;

    // pre-offset gmem row pointers per term (hoists 64-bit IMADs out of the loop)
    const __nv_bfloat16* gA[3];
    const __nv_bfloat16* gB[3];
    {
        const size_t ao = (size_t)(m_base + r_ld) * DIM + h_ld * 32;
        const size_t bo = (size_t)(n_base + r_ld) * DIM + h_ld * 32;
        gA[0] = g_x_hi + ao; gA[1] = g_x_hi + ao; gA[2] = g_x_lo + ao;
        gB[0] = g_w_hi + bo; gB[1] = g_w_lo + bo; gB[2] = g_w_hi + bo;
    }
    // smem store bases (row + half fixed per thread; unit j adds a constant)
    const uint32_t sA_st = sb + r_ld * ROW_B + h_ld * 64;
    const uint32_t sB_st = sA_st + A_BYTES;

    auto load_stage = [&](int it) {
        const int term = it >> 4;
        const int kc   = (it & 15) * 64;
        const uint32_t stb = (uint32_t)((it % NSTAGES) * STAGE_B);
        const __nv_bfloat16* ga = gA[term] + kc;
        const __nv_bfloat16* gb = gB[term] + kc;
#pragma unroll
        for (int j = 0; j < 4; j++) {
            cp_async16(sA_st + stb + j * 16, ga + j * 8);
            cp_async16(sB_st + stb + j * 16, gb + j * 8);
        }
    };

    float acc[4][4][4];
#pragma unroll
    for (int i = 0; i < 4; i++)
#pragma unroll
        for (int j = 0; j < 4; j++)
#pragma unroll
            for (int k = 0; k < 4; k++) acc[i][j][k] = 0.0f;

    // prologue: stages 0..1 in flight
    load_stage(0); cp_commit();
    load_stage(1); cp_commit();

    // per-warp LDSM base addresses (iter-invariant; stage base added per iter)
    // A matrix i, k-step ks:  aWarp + i*(16*ROW_B) + ks*32        (+ uhA*16 folded in)
    // B k-step ks, half uh:   bWarp + ks*32 + uh*16
    const int rA  = lane & 15;
    const int uhA = lane >> 4;
    const uint32_t aWarp = sb + (uint32_t)(wm * 64 + rA) * ROW_B + uhA * 16;
    const uint32_t bWarp = sb + A_BYTES + (uint32_t)(wn * 32 + lane) * ROW_B;

    // double-buffered fragments
    uint32_t a_f[2][4][4];
    uint32_t b_f[2][4][2];

    for (int it = 0; it < ITERS; it++) {
        if (it <= ITERS - 2) cp_wait<1>();
        else                 cp_wait<0>();
        __syncthreads();
        // Top barrier proves every warp finished reading stage (it+2)%3 in iter
        // it-1, so issuing its overwrite now is safe; no trailing barrier needed.
        if (it + 2 < ITERS) { load_stage(it + 2); cp_commit(); }

        const uint32_t stb = (uint32_t)((it % NSTAGES) * STAGE_B);
        const uint32_t aB = aWarp + stb;
        const uint32_t bB = bWarp + stb;

        // preload ks=0 fragments into buffer 0 (all offsets are immediates)
#pragma unroll
        for (int i = 0; i < 4; i++) ldsm_x4(a_f[0][i], aB + i * (16 * ROW_B));
#pragma unroll
        for (int uh = 0; uh < 2; uh++) {
            uint32_t t[4];
            ldsm_x4(t, bB + uh * 16);
            b_f[0][0][uh] = t[0]; b_f[0][1][uh] = t[1];
            b_f[0][2][uh] = t[2]; b_f[0][3][uh] = t[3];
        }

#pragma unroll
        for (int ks = 0; ks < 4; ks++) {
            const int cur = ks & 1, nxt = cur ^ 1;
            if (ks < 3) {
                // prefetch ks+1 fragments while HMMAs of ks issue
#pragma unroll
                for (int i = 0; i < 4; i++)
                    ldsm_x4(a_f[nxt][i], aB + i * (16 * ROW_B) + (ks + 1) * 32);
#pragma unroll
                for (int uh = 0; uh < 2; uh++) {
                    uint32_t t[4];
                    ldsm_x4(t, bB + (ks + 1) * 32 + uh * 16);
                    b_f[nxt][0][uh] = t[0]; b_f[nxt][1][uh] = t[1];
                    b_f[nxt][2][uh] = t[2]; b_f[nxt][3][uh] = t[3];
                }
            }
#pragma unroll
            for (int i = 0; i < 4; i++)
#pragma unroll
                for (int j = 0; j < 4; j++) mma_bf16(acc[i][j], a_f[cur][i], b_f[cur][j]);
        }
    }

    // epilogue: bias + tanh + float2 stores
#pragma unroll
    for (int j = 0; j < 4; j++) {
        const int col0 = n_base + wn * 32 + j * 8 + (lane & 3) * 2;
        const float2 bv = *reinterpret_cast<const float2*>(bias + col0);
#pragma unroll
        for (int i = 0; i < 4; i++) {
            const int row0 = m_base + wm * 64 + i * 16 + (lane >> 2);
            float2 v0, v1;
            v0.x = tanhf(acc[i][j][0] + bv.x);
            v0.y = tanhf(acc[i][j][1] + bv.y);
            v1.x = tanhf(acc[i][j][2] + bv.x);
            v1.y = tanhf(acc[i][j][3] + bv.y);
            *reinterpret_cast<float2*>(out + (size_t)row0 * NOUT + col0) = v0;
            *reinterpret_cast<float2*>(out + (size_t)(row0 + 8) * NOUT + col0) = v1;
        }
    }
}

// ---------------- host launch ----------------
extern "C" void kernel_launch(void* const* d_in, const int* in_sizes, int n_in,
                              void* d_out, int out_size) {
    const float *x = nullptr, *W = nullptr, *b = nullptr;
    for (int i = 0; i < n_in; i++) {
        if (in_sizes[i] == SEQ * DIM)       x = (const float*)d_in[i];
        else if (in_sizes[i] == NOUT * DIM) W = (const float*)d_in[i];
        else if (in_sizes[i] == NOUT)       b = (const float*)d_in[i];
    }
    float* out = (float*)d_out;

    split_all_kernel<<<XBLOCKS + WBLOCKS, 256>>>(x, W);

    static bool attr_set = false;
    if (!attr_set) {
        cudaFuncSetAttribute(gemm_kernel, cudaFuncAttributeMaxDynamicSharedMemorySize, SMEM_GB);
        attr_set = true;
    }
    dim3 grid(NOUT / 128, SEQ / 128);  // (32, 64)
    gemm_kernel<<<grid, 256, SMEM_GB>>>(b, out);
}

// round 9
// speedup vs baseline: 3.2096x; 3.2096x over previous
#include <cuda_runtime.h>
#include <cuda_fp16.h>
#include <cstdint>
#include <math.h>

#define SEQ  8192
#define DIM  1024
#define NOUT 4096

// ---------------- device scratch (no allocations allowed) ----------------
__device__ __half g_x_h[SEQ * DIM];
__device__ __half g_w_h[NOUT * DIM];

// ---------------- PTX helpers (base-target sm_80/sm_90 features only) ----------------
__device__ __forceinline__ uint32_t smem_u32(const void* p) {
    uint32_t a;
    asm("{ .reg .u64 t; cvta.to.shared.u64 t, %1; cvt.u32.u64 %0, t; }" : "=r"(a) : "l"(p));
    return a;
}
__device__ __forceinline__ void cp_async16(uint32_t smem, const void* gmem) {
    asm volatile("cp.async.cg.shared.global [%0], [%1], 16;" :: "r"(smem), "l"(gmem) : "memory");
}
__device__ __forceinline__ void cp_commit() {
    asm volatile("cp.async.commit_group;" ::: "memory");
}
template <int N>
__device__ __forceinline__ void cp_wait() {
    asm volatile("cp.async.wait_group %0;" :: "n"(N) : "memory");
}
__device__ __forceinline__ void ldsm_x4(uint32_t* r, uint32_t addr) {
    asm volatile("ldmatrix.sync.aligned.m8n8.x4.shared.b16 {%0,%1,%2,%3}, [%4];"
                 : "=r"(r[0]), "=r"(r[1]), "=r"(r[2]), "=r"(r[3]) : "r"(addr));
}
__device__ __forceinline__ void mma_f16(float* c, const uint32_t* a, const uint32_t* b) {
    asm volatile(
        "mma.sync.aligned.m16n8k16.row.col.f32.f16.f16.f32 "
        "{%0,%1,%2,%3}, {%4,%5,%6,%7}, {%8,%9}, {%0,%1,%2,%3};"
        : "+f"(c[0]), "+f"(c[1]), "+f"(c[2]), "+f"(c[3])
        : "r"(a[0]), "r"(a[1]), "r"(a[2]), "r"(a[3]), "r"(b[0]), "r"(b[1]));
}

// ---------------- fp32 -> fp16 convert (x and W in ONE kernel) ----------------
static constexpr int XBLOCKS = (SEQ * DIM / 4) / 256;   // 8192
static constexpr int WBLOCKS = (NOUT * DIM / 4) / 256;  // 4096

__global__ void convert_kernel(const float* __restrict__ x, const float* __restrict__ W) {
    const int bid = blockIdx.x;
    const float* src;
    __half* dst;
    int i;
    if (bid < XBLOCKS) {
        src = x; dst = g_x_h;
        i = bid * 256 + threadIdx.x;
    } else {
        src = W; dst = g_w_h;
        i = (bid - XBLOCKS) * 256 + threadIdx.x;
    }
    float4 v = reinterpret_cast<const float4*>(src)[i];
    __half2 h0 = __floats2half2_rn(v.x, v.y);
    __half2 h1 = __floats2half2_rn(v.z, v.w);
    reinterpret_cast<__half2*>(dst)[i * 2 + 0] = h0;
    reinterpret_cast<__half2*>(dst)[i * 2 + 1] = h1;
}

// ---------------- mma.sync GEMM + bias + tanh (fp16 single-term) ----------------
// CTA tile 128x128, K-stage 64 fp16 -> 16 stage-iterations.
// 8 warps in 2(M) x 4(N) grid; warp tile 64x32 via m16n8k16.
// XOR-swizzled smem (conflict-free LDSM/STS); 3 cp.async stages; 2 CTAs/SM.
static constexpr int NSTAGES  = 3;
static constexpr int A_BYTES  = 128 * 128;          // 128 rows x 64 fp16 (128B/row)
static constexpr int STAGE_B  = 2 * A_BYTES;        // A + B = 32 KB
static constexpr int SMEM_GB  = NSTAGES * STAGE_B;  // 96 KB
static constexpr int ITERS    = DIM / 64;           // 16

__global__ __launch_bounds__(256, 2)
void gemm_kernel(const float* __restrict__ bias, float* __restrict__ out) {
    extern __shared__ char smem[];
    const uint32_t sb = smem_u32(smem);
    const int tid  = threadIdx.x;
    const int lane = tid & 31;
    const int wid  = tid >> 5;
    const int wm   = wid >> 2;       // 0..1 -> 64 rows
    const int wn   = wid & 3;        // 0..3 -> 32 cols
    const int m_base = blockIdx.y * 128;
    const int n_base = blockIdx.x * 128;

    // cp.async addressing: thread t -> row r = t>>1 (0..127), half h = t&1, 4x16B units
    const int r_ld = tid >> 1;
    const int h_ld = tid & 1;

    const __half* ga0 = g_x_h + (size_t)(m_base + r_ld) * DIM;
    const __half* gb0 = g_w_h + (size_t)(n_base + r_ld) * DIM;

    auto load_stage = [&](int it) {
        const int kc = it * 64;
        const int st = (it % NSTAGES) * STAGE_B;
        const __half* ga = ga0 + kc;
        const __half* gb = gb0 + kc;
        const uint32_t sa  = sb + st + r_ld * 128;
        const uint32_t sbb = sb + st + A_BYTES + r_ld * 128;
        const int swz = r_ld & 7;
#pragma unroll
        for (int j = 0; j < 4; j++) {
            const int u = h_ld * 4 + j;
            const uint32_t so = (uint32_t)((u ^ swz) << 4);
            cp_async16(sa + so, ga + u * 8);
            cp_async16(sbb + so, gb + u * 8);
        }
    };

    float acc[4][4][4];
#pragma unroll
    for (int i = 0; i < 4; i++)
#pragma unroll
        for (int j = 0; j < 4; j++)
#pragma unroll
            for (int k = 0; k < 4; k++) acc[i][j][k] = 0.0f;

    // prologue: stages 0..1 in flight
    load_stage(0); cp_commit();
    load_stage(1); cp_commit();

    // per-lane ldmatrix row constants
    const int rA  = lane & 15;        // A: row within m16 tile
    const int uhA = lane >> 4;        // A: k 16B-unit half
    const int rB  = lane;             // B: row within warp's 32 n-rows (4 n-tiles)
    const int rowAc[4] = {wm * 64 + 0 * 16 + rA, wm * 64 + 1 * 16 + rA,
                          wm * 64 + 2 * 16 + rA, wm * 64 + 3 * 16 + rA};
    const int rowBc = wn * 32 + rB;

    // double-buffered fragments
    uint32_t a_f[2][4][4];
    uint32_t b_f[2][4][2];

    for (int it = 0; it < ITERS; it++) {
        if (it <= ITERS - 2) cp_wait<1>();
        else                 cp_wait<0>();
        __syncthreads();
        // Top barrier proves every warp finished reading stage (it+2)%3 in iter
        // it-1, so issuing its overwrite now is safe; no trailing barrier needed.
        if (it + 2 < ITERS) { load_stage(it + 2); cp_commit(); }

        const uint32_t aBase = sb + (it % NSTAGES) * STAGE_B;
        const uint32_t bBase = aBase + A_BYTES;

        // preload ks=0 fragments into buffer 0
#pragma unroll
        for (int i = 0; i < 4; i++) {
            const uint32_t u = (uint32_t)(uhA ^ (rowAc[i] & 7));
            ldsm_x4(a_f[0][i], aBase + rowAc[i] * 128 + (u << 4));
        }
#pragma unroll
        for (int uh = 0; uh < 2; uh++) {
            const uint32_t u = (uint32_t)(uh ^ (rowBc & 7));
            uint32_t t[4];
            ldsm_x4(t, bBase + rowBc * 128 + (u << 4));
            b_f[0][0][uh] = t[0]; b_f[0][1][uh] = t[1];
            b_f[0][2][uh] = t[2]; b_f[0][3][uh] = t[3];
        }

#pragma unroll
        for (int ks = 0; ks < 4; ks++) {
            const int cur = ks & 1, nxt = cur ^ 1;
            if (ks < 3) {
                // prefetch ks+1 fragments while HMMAs of ks issue
#pragma unroll
                for (int i = 0; i < 4; i++) {
                    const uint32_t u = (uint32_t)(((ks + 1) * 2 + uhA) ^ (rowAc[i] & 7));
                    ldsm_x4(a_f[nxt][i], aBase + rowAc[i] * 128 + (u << 4));
                }
#pragma unroll
                for (int uh = 0; uh < 2; uh++) {
                    const uint32_t u = (uint32_t)(((ks + 1) * 2 + uh) ^ (rowBc & 7));
                    uint32_t t[4];
                    ldsm_x4(t, bBase + rowBc * 128 + (u << 4));
                    b_f[nxt][0][uh] = t[0]; b_f[nxt][1][uh] = t[1];
                    b_f[nxt][2][uh] = t[2]; b_f[nxt][3][uh] = t[3];
                }
            }
#pragma unroll
            for (int i = 0; i < 4; i++)
#pragma unroll
                for (int j = 0; j < 4; j++) mma_f16(acc[i][j], a_f[cur][i], b_f[cur][j]);
        }
    }

    // epilogue: bias + tanh + float2 stores
#pragma unroll
    for (int j = 0; j < 4; j++) {
        const int col0 = n_base + wn * 32 + j * 8 + (lane & 3) * 2;
        const float2 bv = *reinterpret_cast<const float2*>(bias + col0);
#pragma unroll
        for (int i = 0; i < 4; i++) {
            const int row0 = m_base + wm * 64 + i * 16 + (lane >> 2);
            float2 v0, v1;
            v0.x = tanhf(acc[i][j][0] + bv.x);
            v0.y = tanhf(acc[i][j][1] + bv.y);
            v1.x = tanhf(acc[i][j][2] + bv.x);
            v1.y = tanhf(acc[i][j][3] + bv.y);
            *reinterpret_cast<float2*>(out + (size_t)row0 * NOUT + col0) = v0;
            *reinterpret_cast<float2*>(out + (size_t)(row0 + 8) * NOUT + col0) = v1;
        }
    }
}

// ---------------- host launch ----------------
extern "C" void kernel_launch(void* const* d_in, const int* in_sizes, int n_in,
                              void* d_out, int out_size) {
    const float *x = nullptr, *W = nullptr, *b = nullptr;
    for (int i = 0; i < n_in; i++) {
        if (in_sizes[i] == SEQ * DIM)       x = (const float*)d_in[i];
        else if (in_sizes[i] == NOUT * DIM) W = (const float*)d_in[i];
        else if (in_sizes[i] == NOUT)       b = (const float*)d_in[i];
    }
    float* out = (float*)d_out;

    convert_kernel<<<XBLOCKS + WBLOCKS, 256>>>(x, W);

    static bool attr_set = false;
    if (!attr_set) {
        cudaFuncSetAttribute(gemm_kernel, cudaFuncAttributeMaxDynamicSharedMemorySize, SMEM_GB);
        attr_set = true;
    }
    dim3 grid(NOUT / 128, SEQ / 128);  // (32, 64)
    gemm_kernel<<<grid, 256, SMEM_GB>>>(b, out);
}

// round 10
// speedup vs baseline: 3.2408x; 1.0097x over previous
#include <cuda_runtime.h>
#include <cuda_fp16.h>
#include <cstdint>
#include <math.h>

#define SEQ  8192
#define DIM  1024
#define NOUT 4096

// ---------------- device scratch (no allocations allowed) ----------------
__device__ __half g_x_h[SEQ * DIM];
__device__ __half g_w_h[NOUT * DIM];

// ---------------- PTX helpers (base-target sm_80/sm_90 features only) ----------------
__device__ __forceinline__ uint32_t smem_u32(const void* p) {
    uint32_t a;
    asm("{ .reg .u64 t; cvta.to.shared.u64 t, %1; cvt.u32.u64 %0, t; }" : "=r"(a) : "l"(p));
    return a;
}
template <int SRC_OFF>
__device__ __forceinline__ void cp16(uint32_t dst, const void* src) {
    asm volatile("cp.async.cg.shared.global [%0], [%1+%2], 16;"
                 :: "r"(dst), "l"(src), "n"(SRC_OFF) : "memory");
}
template <int DST_OFF, int SRC_OFF>
__device__ __forceinline__ void cp16_d(uint32_t dst, const void* src) {
    asm volatile("cp.async.cg.shared.global [%0+%2], [%1+%3], 16;"
                 :: "r"(dst), "l"(src), "n"(DST_OFF), "n"(SRC_OFF) : "memory");
}
__device__ __forceinline__ void cp_commit() {
    asm volatile("cp.async.commit_group;" ::: "memory");
}
template <int N>
__device__ __forceinline__ void cp_wait() {
    asm volatile("cp.async.wait_group %0;" :: "n"(N) : "memory");
}
// ldmatrix with compile-time immediate offset: address ALU hoists out of the loop.
template <int IMM>
__device__ __forceinline__ void ldsm_x4_i(uint32_t* r, uint32_t addr) {
    asm volatile("ldmatrix.sync.aligned.m8n8.x4.shared.b16 {%0,%1,%2,%3}, [%4+%5];"
                 : "=r"(r[0]), "=r"(r[1]), "=r"(r[2]), "=r"(r[3])
                 : "r"(addr), "n"(IMM));
}
__device__ __forceinline__ void mma_f16(float* c, const uint32_t* a, const uint32_t* b) {
    asm volatile(
        "mma.sync.aligned.m16n8k16.row.col.f32.f16.f16.f32 "
        "{%0,%1,%2,%3}, {%4,%5,%6,%7}, {%8,%9}, {%0,%1,%2,%3};"
        : "+f"(c[0]), "+f"(c[1]), "+f"(c[2]), "+f"(c[3])
        : "r"(a[0]), "r"(a[1]), "r"(a[2]), "r"(a[3]), "r"(b[0]), "r"(b[1]));
}

// ---------------- fp32 -> fp16 convert (x and W in ONE kernel) ----------------
static constexpr int XBLOCKS = (SEQ * DIM / 4) / 256;   // 8192
static constexpr int WBLOCKS = (NOUT * DIM / 4) / 256;  // 4096

__global__ void convert_kernel(const float* __restrict__ x, const float* __restrict__ W) {
    const int bid = blockIdx.x;
    const float* src;
    __half* dst;
    int i;
    if (bid < XBLOCKS) {
        src = x; dst = g_x_h;
        i = bid * 256 + threadIdx.x;
    } else {
        src = W; dst = g_w_h;
        i = (bid - XBLOCKS) * 256 + threadIdx.x;
    }
    float4 v = reinterpret_cast<const float4*>(src)[i];
    __half2 h0 = __floats2half2_rn(v.x, v.y);
    __half2 h1 = __floats2half2_rn(v.z, v.w);
    reinterpret_cast<__half2*>(dst)[i * 2 + 0] = h0;
    reinterpret_cast<__half2*>(dst)[i * 2 + 1] = h1;
}

// ---------------- mma.sync GEMM + bias + tanh (fp16 single-term) ----------------
// CTA tile 128x128, K-stage 64 fp16 -> 16 stage-iterations.
// 8 warps in 2(M) x 4(N) grid; warp tile 64x32 via m16n8k16.
// XOR-swizzled smem, but ALL swizzle algebra precomputed per-lane:
//   ((ks*2+uh)^swz)<<4  ==  (ks<<5) ^ ((swz^uh)<<4)   (no carries into XOR bits)
// so per-iter addressing is 1 IADD per LDSM group + instruction immediates.
static constexpr int NSTAGES  = 3;
static constexpr int A_BYTES  = 128 * 128;          // 128 rows x 64 fp16 (128B/row)
static constexpr int STAGE_B  = 2 * A_BYTES;        // A + B = 32 KB
static constexpr int SMEM_GB  = NSTAGES * STAGE_B;  // 96 KB
static constexpr int ITERS    = DIM / 64;           // 16

__global__ __launch_bounds__(256, 2)
void gemm_kernel(const float* __restrict__ bias, float* __restrict__ out) {
    extern __shared__ char smem[];
    const uint32_t sb = smem_u32(smem);
    const int tid  = threadIdx.x;
    const int lane = tid & 31;
    const int wid  = tid >> 5;
    const int wm   = wid >> 2;       // 0..1 -> 64 rows
    const int wn   = wid & 3;        // 0..3 -> 32 cols
    const int m_base = blockIdx.y * 128;
    const int n_base = blockIdx.x * 128;

    // ---- cp.async lane constants: thread t -> row r_ld, half h_ld, 4x16B units
    const int r_ld = tid >> 1;
    const int h_ld = tid & 1;
    const int swzL = r_ld & 7;
    // dst offsets for the 4 16B units (swizzle folded per-lane)
    uint32_t sOff[4];
#pragma unroll
    for (int j = 0; j < 4; j++) sOff[j] = (uint32_t)(((h_ld * 4 + j) ^ swzL) << 4);
    const uint32_t sAst = sb + (uint32_t)r_ld * 128;            // + stage base per iter
    // gmem row pointers with h_ld folded in; advance by 64 elements per iter
    const __half* gaP = g_x_h + (size_t)(m_base + r_ld) * DIM + h_ld * 32 + 2 * 64;
    const __half* gbP = g_w_h + (size_t)(n_base + r_ld) * DIM + h_ld * 32 + 2 * 64;

    // ---- LDSM lane constants
    const int rA  = lane & 15;        // A: row within m16 tile
    const int uhA = lane >> 4;        // A: k 16B-unit half
    const uint32_t mA = (uint32_t)(((rA & 7) ^ uhA) << 4);
    const uint32_t mB = (uint32_t)((lane & 7) << 4);
    uint32_t xA[4], xB[8];
#pragma unroll
    for (int ks = 0; ks < 4; ks++) xA[ks] = (uint32_t)(ks << 5) ^ mA;
#pragma unroll
    for (int u = 0; u < 8; u++) xB[u] = (uint32_t)(u << 4) ^ mB;
    const uint32_t aWarp = sb + (uint32_t)(wm * 64 + rA) * 128;
    const uint32_t bWarp = sb + A_BYTES + (uint32_t)(wn * 32 + lane) * 128;

    float acc[4][4][4];
#pragma unroll
    for (int i = 0; i < 4; i++)
#pragma unroll
        for (int j = 0; j < 4; j++)
#pragma unroll
            for (int k = 0; k < 4; k++) acc[i][j][k] = 0.0f;

    // ---- prologue: stages 0..1 in flight
    {
        const __half* ga = gaP - 2 * 64;
        const __half* gb = gbP - 2 * 64;
#pragma unroll
        for (int s = 0; s < 2; s++) {
            const uint32_t d = sAst + (uint32_t)(s * STAGE_B);
            cp16<0>(d + sOff[0], ga);  cp16_d<A_BYTES, 0>(d + sOff[0], gb);
            cp16<16>(d + sOff[1], ga); cp16_d<A_BYTES, 16>(d + sOff[1], gb);
            cp16<32>(d + sOff[2], ga); cp16_d<A_BYTES, 32>(d + sOff[2], gb);
            cp16<48>(d + sOff[3], ga); cp16_d<A_BYTES, 48>(d + sOff[3], gb);
            cp_commit();
            ga += 64; gb += 64;
        }
    }

    // double-buffered fragments
    uint32_t a_f[2][4][4];
    uint32_t b_f[2][4][2];

    uint32_t stb  = 0;                       // consume stage base
    uint32_t stb2 = 2 * STAGE_B;             // produce stage base (it+2)

    for (int it = 0; it < ITERS; it++) {
        if (it <= ITERS - 2) cp_wait<1>();
        else                 cp_wait<0>();
        __syncthreads();
        // Top barrier proves every warp finished reading stage (it+2)%3 in iter
        // it-1, so issuing its overwrite now is safe; no trailing barrier needed.
        if (it + 2 < ITERS) {
            const uint32_t d = sAst + stb2;
            cp16<0>(d + sOff[0], gaP);  cp16_d<A_BYTES, 0>(d + sOff[0], gbP);
            cp16<16>(d + sOff[1], gaP); cp16_d<A_BYTES, 16>(d + sOff[1], gbP);
            cp16<32>(d + sOff[2], gaP); cp16_d<A_BYTES, 32>(d + sOff[2], gbP);
            cp16<48>(d + sOff[3], gaP); cp16_d<A_BYTES, 48>(d + sOff[3], gbP);
            cp_commit();
            gaP += 64; gbP += 64;
            stb2 += STAGE_B; if (stb2 == SMEM_GB) stb2 = 0;
        }

        const uint32_t aIt = aWarp + stb;
        const uint32_t bIt = bWarp + stb;
        stb += STAGE_B; if (stb == SMEM_GB) stb = 0;

        // preload ks=0 fragments into buffer 0 (row offsets are immediates)
        {
            const uint32_t aA = aIt + xA[0];
            ldsm_x4_i<0>(a_f[0][0], aA);
            ldsm_x4_i<2048>(a_f[0][1], aA);
            ldsm_x4_i<4096>(a_f[0][2], aA);
            ldsm_x4_i<6144>(a_f[0][3], aA);
            uint32_t t0[4], t1[4];
            ldsm_x4_i<0>(t0, bIt + xB[0]);
            ldsm_x4_i<0>(t1, bIt + xB[1]);
            b_f[0][0][0] = t0[0]; b_f[0][1][0] = t0[1]; b_f[0][2][0] = t0[2]; b_f[0][3][0] = t0[3];
            b_f[0][0][1] = t1[0]; b_f[0][1][1] = t1[1]; b_f[0][2][1] = t1[2]; b_f[0][3][1] = t1[3];
        }

#pragma unroll
        for (int ks = 0; ks < 4; ks++) {
            const int cur = ks & 1, nxt = cur ^ 1;
            if (ks < 3) {
                // prefetch ks+1 fragments while HMMAs of ks issue
                const uint32_t aA = aIt + xA[ks + 1];
                ldsm_x4_i<0>(a_f[nxt][0], aA);
                ldsm_x4_i<2048>(a_f[nxt][1], aA);
                ldsm_x4_i<4096>(a_f[nxt][2], aA);
                ldsm_x4_i<6144>(a_f[nxt][3], aA);
                uint32_t t0[4], t1[4];
                ldsm_x4_i<0>(t0, bIt + xB[2 * (ks + 1)]);
                ldsm_x4_i<0>(t1, bIt + xB[2 * (ks + 1) + 1]);
                b_f[nxt][0][0] = t0[0]; b_f[nxt][1][0] = t0[1]; b_f[nxt][2][0] = t0[2]; b_f[nxt][3][0] = t0[3];
                b_f[nxt][0][1] = t1[0]; b_f[nxt][1][1] = t1[1]; b_f[nxt][2][1] = t1[2]; b_f[nxt][3][1] = t1[3];
            }
#pragma unroll
            for (int i = 0; i < 4; i++)
#pragma unroll
                for (int j = 0; j < 4; j++) mma_f16(acc[i][j], a_f[cur][i], b_f[cur][j]);
        }
    }

    // epilogue: bias + tanh + float2 stores
#pragma unroll
    for (int j = 0; j < 4; j++) {
        const int col0 = n_base + wn * 32 + j * 8 + (lane & 3) * 2;
        const float2 bv = *reinterpret_cast<const float2*>(bias + col0);
#pragma unroll
        for (int i = 0; i < 4; i++) {
            const int row0 = m_base + wm * 64 + i * 16 + (lane >> 2);
            float2 v0, v1;
            v0.x = tanhf(acc[i][j][0] + bv.x);
            v0.y = tanhf(acc[i][j][1] + bv.y);
            v1.x = tanhf(acc[i][j][2] + bv.x);
            v1.y = tanhf(acc[i][j][3] + bv.y);
            *reinterpret_cast<float2*>(out + (size_t)row0 * NOUT + col0) = v0;
            *reinterpret_cast<float2*>(out + (size_t)(row0 + 8) * NOUT + col0) = v1;
        }
    }
}

// ---------------- host launch ----------------
extern "C" void kernel_launch(void* const* d_in, const int* in_sizes, int n_in,
                              void* d_out, int out_size) {
    const float *x = nullptr, *W = nullptr, *b = nullptr;
    for (int i = 0; i < n_in; i++) {
        if (in_sizes[i] == SEQ * DIM)       x = (const float*)d_in[i];
        else if (in_sizes[i] == NOUT * DIM) W = (const float*)d_in[i];
        else if (in_sizes[i] == NOUT)       b = (const float*)d_in[i];
    }
    float* out = (float*)d_out;

    convert_kernel<<<XBLOCKS + WBLOCKS, 256>>>(x, W);

    static bool attr_set = false;
    if (!attr_set) {
        cudaFuncSetAttribute(gemm_kernel, cudaFuncAttributeMaxDynamicSharedMemorySize, SMEM_GB);
        attr_set = true;
    }
    dim3 grid(NOUT / 128, SEQ / 128);  // (32, 64)
    gemm_kernel<<<grid, 256, SMEM_GB>>>(b, out);
}

// round 11
// speedup vs baseline: 3.3004x; 1.0184x over previous
#include <cuda_runtime.h>
#include <cuda_fp16.h>
#include <cstdint>
#include <math.h>

#define SEQ  8192
#define DIM  1024
#define NOUT 4096

// ---------------- device scratch (no allocations allowed) ----------------
__device__ __half g_x_h[SEQ * DIM];
__device__ __half g_w_h[NOUT * DIM];

// ---------------- PTX helpers (base-target sm_80/sm_90 features only) ----------------
__device__ __forceinline__ uint32_t smem_u32(const void* p) {
    uint32_t a;
    asm("{ .reg .u64 t; cvta.to.shared.u64 t, %1; cvt.u32.u64 %0, t; }" : "=r"(a) : "l"(p));
    return a;
}
template <int DST_OFF, int SRC_OFF>
__device__ __forceinline__ void cp16_d(uint32_t dst, const void* src) {
    asm volatile("cp.async.cg.shared.global [%0+%2], [%1+%3], 16;"
                 :: "r"(dst), "l"(src), "n"(DST_OFF), "n"(SRC_OFF) : "memory");
}
__device__ __forceinline__ void cp_commit() {
    asm volatile("cp.async.commit_group;" ::: "memory");
}
template <int N>
__device__ __forceinline__ void cp_wait() {
    asm volatile("cp.async.wait_group %0;" :: "n"(N) : "memory");
}
template <int IMM>
__device__ __forceinline__ void ldsm_x4_i(uint32_t* r, uint32_t addr) {
    asm volatile("ldmatrix.sync.aligned.m8n8.x4.shared.b16 {%0,%1,%2,%3}, [%4+%5];"
                 : "=r"(r[0]), "=r"(r[1]), "=r"(r[2]), "=r"(r[3])
                 : "r"(addr), "n"(IMM));
}
__device__ __forceinline__ void mma_f16(float* c, const uint32_t* a, const uint32_t* b) {
    asm volatile(
        "mma.sync.aligned.m16n8k16.row.col.f32.f16.f16.f32 "
        "{%0,%1,%2,%3}, {%4,%5,%6,%7}, {%8,%9}, {%0,%1,%2,%3};"
        : "+f"(c[0]), "+f"(c[1]), "+f"(c[2]), "+f"(c[3])
        : "r"(a[0]), "r"(a[1]), "r"(a[2]), "r"(a[3]), "r"(b[0]), "r"(b[1]));
}
// fast tanh: 1 - 2/(e^{2x}+1); saturates correctly at +/-inf; err << 3e-4 budget
__device__ __forceinline__ float ftanh(float x) {
    float e = __expf(2.0f * x);
    return 1.0f - __fdividef(2.0f, e + 1.0f);
}

// ---------------- fp32 -> fp16 convert (x and W in ONE kernel) ----------------
static constexpr int XBLOCKS = (SEQ * DIM / 4) / 256;   // 8192
static constexpr int WBLOCKS = (NOUT * DIM / 4) / 256;  // 4096

__global__ void convert_kernel(const float* __restrict__ x, const float* __restrict__ W) {
    const int bid = blockIdx.x;
    const float* src;
    __half* dst;
    int i;
    if (bid < XBLOCKS) {
        src = x; dst = g_x_h;
        i = bid * 256 + threadIdx.x;
    } else {
        src = W; dst = g_w_h;
        i = (bid - XBLOCKS) * 256 + threadIdx.x;
    }
    float4 v = reinterpret_cast<const float4*>(src)[i];
    __half2 h0 = __floats2half2_rn(v.x, v.y);
    __half2 h1 = __floats2half2_rn(v.z, v.w);
    reinterpret_cast<__half2*>(dst)[i * 2 + 0] = h0;
    reinterpret_cast<__half2*>(dst)[i * 2 + 1] = h1;
}

// ---------------- mma.sync GEMM + bias + tanh (fp16 single-term) ----------------
// CTA tile 128x128, K-stage 64 fp16 -> 16 stage-iterations, 8 warps (2M x 4N).
// Rolled software pipeline: next-iter ks0 fragments are loaded during ks3 of the
// current iter (after wait+sync), so the tensor pipe never drains at barriers.
static constexpr int NSTAGES  = 3;
static constexpr int A_BYTES  = 128 * 128;          // 128 rows x 64 fp16 (128B/row)
static constexpr int STAGE_B  = 2 * A_BYTES;        // A + B = 32 KB
static constexpr int SMEM_GB  = NSTAGES * STAGE_B;  // 96 KB
static constexpr int ITERS    = DIM / 64;           // 16

__global__ __launch_bounds__(256, 2)
void gemm_kernel(const float* __restrict__ bias, float* __restrict__ out) {
    extern __shared__ char smem[];
    const uint32_t sb = smem_u32(smem);
    const int tid  = threadIdx.x;
    const int lane = tid & 31;
    const int wid  = tid >> 5;
    const int wm   = wid >> 2;       // 0..1 -> 64 rows
    const int wn   = wid & 3;        // 0..3 -> 32 cols
    const int m_base = blockIdx.y * 128;
    const int n_base = blockIdx.x * 128;

    // ---- cp.async lane constants
    const int r_ld = tid >> 1;
    const int h_ld = tid & 1;
    const int swzL = r_ld & 7;
    uint32_t sOff[4];
#pragma unroll
    for (int j = 0; j < 4; j++) sOff[j] = (uint32_t)(((h_ld * 4 + j) ^ swzL) << 4);
    const uint32_t sAst = sb + (uint32_t)r_ld * 128;
    const __half* gaP = g_x_h + (size_t)(m_base + r_ld) * DIM + h_ld * 32 + 2 * 64;
    const __half* gbP = g_w_h + (size_t)(n_base + r_ld) * DIM + h_ld * 32 + 2 * 64;

    // ---- LDSM lane constants (swizzle algebra precomputed)
    const int rA  = lane & 15;
    const int uhA = lane >> 4;
    const uint32_t mA = (uint32_t)(((rA & 7) ^ uhA) << 4);
    const uint32_t mB = (uint32_t)((lane & 7) << 4);
    uint32_t xA[4], xB[8];
#pragma unroll
    for (int ks = 0; ks < 4; ks++) xA[ks] = (uint32_t)(ks << 5) ^ mA;
#pragma unroll
    for (int u = 0; u < 8; u++) xB[u] = (uint32_t)(u << 4) ^ mB;
    const uint32_t aWarp = sb + (uint32_t)(wm * 64 + rA) * 128;
    const uint32_t bWarp = sb + A_BYTES + (uint32_t)(wn * 32 + lane) * 128;

    float acc[4][4][4];
#pragma unroll
    for (int i = 0; i < 4; i++)
#pragma unroll
        for (int j = 0; j < 4; j++)
#pragma unroll
            for (int k = 0; k < 4; k++) acc[i][j][k] = 0.0f;

    // frag buffers: buf[ks&1] holds k-step ks (ks0 of next iter lands in buf0: 4k steps/iter)
    uint32_t a_f[2][4][4];
    uint32_t b_f[2][4][2];

    // A-fragment loader: group g (ks or next-ks0) from stage base 'stage'
    auto ld_a = [&](uint32_t* dst4x4, uint32_t stage, uint32_t xa) {
        const uint32_t aA = aWarp + stage + xa;
        ldsm_x4_i<0>(dst4x4 + 0, aA);
        ldsm_x4_i<2048>(dst4x4 + 4, aA);
        ldsm_x4_i<4096>(dst4x4 + 8, aA);
        ldsm_x4_i<6144>(dst4x4 + 12, aA);
    };
    auto ld_b = [&](uint32_t (*dstb)[2], uint32_t stage, uint32_t xb0, uint32_t xb1) {
        uint32_t t0[4], t1[4];
        const uint32_t bB = bWarp + stage;
        ldsm_x4_i<0>(t0, bB + xb0);
        ldsm_x4_i<0>(t1, bB + xb1);
        dstb[0][0] = t0[0]; dstb[1][0] = t0[1]; dstb[2][0] = t0[2]; dstb[3][0] = t0[3];
        dstb[0][1] = t1[0]; dstb[1][1] = t1[1]; dstb[2][1] = t1[2]; dstb[3][1] = t1[3];
    };
    auto issue_stage = [&](uint32_t stb2) {
        const uint32_t d = sAst + stb2;
        cp16_d<0, 0>(d + sOff[0], gaP);  cp16_d<A_BYTES, 0>(d + sOff[0], gbP);
        cp16_d<0, 16>(d + sOff[1], gaP); cp16_d<A_BYTES, 16>(d + sOff[1], gbP);
        cp16_d<0, 32>(d + sOff[2], gaP); cp16_d<A_BYTES, 32>(d + sOff[2], gbP);
        cp16_d<0, 48>(d + sOff[3], gaP); cp16_d<A_BYTES, 48>(d + sOff[3], gbP);
        cp_commit();
        gaP += 64; gbP += 64;
    };

    // ---- prologue: issue stages 0,1; wait stage0; preload ks0 fragments
    {
        const __half* ga = gaP - 2 * 64;
        const __half* gb = gbP - 2 * 64;
#pragma unroll
        for (int s = 0; s < 2; s++) {
            const uint32_t d = sAst + (uint32_t)(s * STAGE_B);
            cp16_d<0, 0>(d + sOff[0], ga);  cp16_d<A_BYTES, 0>(d + sOff[0], gb);
            cp16_d<0, 16>(d + sOff[1], ga); cp16_d<A_BYTES, 16>(d + sOff[1], gb);
            cp16_d<0, 32>(d + sOff[2], ga); cp16_d<A_BYTES, 32>(d + sOff[2], gb);
            cp16_d<0, 48>(d + sOff[3], ga); cp16_d<A_BYTES, 48>(d + sOff[3], gb);
            cp_commit();
            ga += 64; gb += 64;
        }
    }
    cp_wait<1>();
    __syncthreads();
    ld_a(&a_f[0][0][0], 0, xA[0]);
    ld_b(b_f[0], 0, xB[0], xB[1]);

    uint32_t stb  = 0;                 // stage being consumed this iter
    uint32_t stb2 = 2 * STAGE_B;       // stage being produced (it+2)

    for (int it = 0; it < ITERS; it++) {
#pragma unroll
        for (int ks = 0; ks < 4; ks++) {
            const int cur = ks & 1, nxt = cur ^ 1;
            if (ks == 0) {
                // prefetch ks1 first (LDSM latency covered by cp-issue + mma below)
                ld_a(&a_f[nxt][0][0], stb, xA[1]);
                ld_b(b_f[nxt], stb, xB[2], xB[3]);
                // produce stage it+2 (overwrites stage it-1; barrier at iter it-1
                // ks3 proves all warps finished reading it)
                if (it + 2 < ITERS) {
                    issue_stage(stb2);
                    stb2 += STAGE_B; if (stb2 == SMEM_GB) stb2 = 0;
                }
            } else if (ks < 3) {
                ld_a(&a_f[nxt][0][0], stb, xA[ks + 1]);
                ld_b(b_f[nxt], stb, xB[2 * (ks + 1)], xB[2 * (ks + 1) + 1]);
            } else if (it + 1 < ITERS) {
                // ks3: next stage has arrived; sync, then load next-iter ks0.
                // Warps still hold ks3 fragments -> tensor pipe stays fed.
                if (it < ITERS - 2) cp_wait<1>();
                else                cp_wait<0>();
                __syncthreads();
                uint32_t stbN = stb + STAGE_B; if (stbN == SMEM_GB) stbN = 0;
                ld_a(&a_f[nxt][0][0], stbN, xA[0]);
                ld_b(b_f[nxt], stbN, xB[0], xB[1]);
            }
#pragma unroll
            for (int i = 0; i < 4; i++)
#pragma unroll
                for (int j = 0; j < 4; j++) mma_f16(acc[i][j], a_f[cur][i], b_f[cur][j]);
        }
        stb += STAGE_B; if (stb == SMEM_GB) stb = 0;
    }

    // epilogue: bias + fast tanh + float2 stores
#pragma unroll
    for (int j = 0; j < 4; j++) {
        const int col0 = n_base + wn * 32 + j * 8 + (lane & 3) * 2;
        const float2 bv = *reinterpret_cast<const float2*>(bias + col0);
#pragma unroll
        for (int i = 0; i < 4; i++) {
            const int row0 = m_base + wm * 64 + i * 16 + (lane >> 2);
            float2 v0, v1;
            v0.x = ftanh(acc[i][j][0] + bv.x);
            v0.y = ftanh(acc[i][j][1] + bv.y);
            v1.x = ftanh(acc[i][j][2] + bv.x);
            v1.y = ftanh(acc[i][j][3] + bv.y);
            *reinterpret_cast<float2*>(out + (size_t)row0 * NOUT + col0) = v0;
            *reinterpret_cast<float2*>(out + (size_t)(row0 + 8) * NOUT + col0) = v1;
        }
    }
}

// ---------------- host launch ----------------
extern "C" void kernel_launch(void* const* d_in, const int* in_sizes, int n_in,
                              void* d_out, int out_size) {
    const float *x = nullptr, *W = nullptr, *b = nullptr;
    for (int i = 0; i < n_in; i++) {
        if (in_sizes[i] == SEQ * DIM)       x = (const float*)d_in[i];
        else if (in_sizes[i] == NOUT * DIM) W = (const float*)d_in[i];
        else if (in_sizes[i] == NOUT)       b = (const float*)d_in[i];
    }
    float* out = (float*)d_out;

    convert_kernel<<<XBLOCKS + WBLOCKS, 256>>>(x, W);

    static bool attr_set = false;
    if (!attr_set) {
        cudaFuncSetAttribute(gemm_kernel, cudaFuncAttributeMaxDynamicSharedMemorySize, SMEM_GB);
        attr_set = true;
    }
    dim3 grid(NOUT / 128, SEQ / 128);  // (32, 64)
    gemm_kernel<<<grid, 256, SMEM_GB>>>(b, out);
}